// round 6
// baseline (speedup 1.0000x reference)
#include <cuda_runtime.h>
#include <cstdint>

#define DINLINE __device__ __forceinline__

// ---------------- geometry ----------------
#define DTILE 384         // edges per tile (8 warps x 48 rows)
#define WROWS 48
#define KDIM  256
#define HDIM  64
#define RING  5           // cp.async ring slots per warp
#define CHUNK_B 3072      // 48 rows x 16 cols x 4B
#define NCHUNK 16         // chunks per tile (16 cols each)

// ---------------- smem layout ----------------
#define OFF_W1F  0                       // 32kt x 8nt x 32 lanes x float2 = 65536
#define OFF_W2F  65536                   // 8kt x 8nt x 32 x float2 = 16384
#define OFF_CMB  81920                   // 8 warps x RING x CHUNK_B = 122880
#define OFF_B1   204800                  // 256B
#define OFF_B2   205056                  // 256B
#define OFF_FLAG 205312                  // 4B
#define SMEM_TOTAL 205440                // < 232448

// ---------------- helpers ----------------
DINLINE float tf32r(float x) {   // round fp32 -> tf32 (rna), keep as fp32 bits
    uint32_t u;
    asm("cvt.rna.tf32.f32 %0, %1;" : "=r"(u) : "f"(x));
    return __uint_as_float(u);
}

DINLINE uint32_t s2u(const void* p) {
    uint32_t a;
    asm("{ .reg .u64 t; cvta.to.shared.u64 t, %1; cvt.u32.u64 %0, t; }" : "=r"(a) : "l"(p));
    return a;
}

DINLINE void cp16(uint32_t dst, const void* src) {
    asm volatile("cp.async.cg.shared.global [%0], [%1], 16;" :: "r"(dst), "l"(src));
}
DINLINE void cp_commit() { asm volatile("cp.async.commit_group;" ::: "memory"); }
template <int N> DINLINE void cp_wait() {
    asm volatile("cp.async.wait_group %0;" :: "n"(N) : "memory");
}

// D += A(m16k8,row) * B(k8n8,col), tf32 in / f32 out
DINLINE void mma8(float* c, uint32_t a0, uint32_t a1, uint32_t a2, uint32_t a3,
                  uint32_t b0, uint32_t b1) {
    asm volatile(
        "mma.sync.aligned.m16n8k8.row.col.f32.tf32.tf32.f32 "
        "{%0,%1,%2,%3}, {%4,%5,%6,%7}, {%8,%9}, {%0,%1,%2,%3};"
        : "+f"(c[0]), "+f"(c[1]), "+f"(c[2]), "+f"(c[3])
        : "r"(a0), "r"(a1), "r"(a2), "r"(a3), "r"(b0), "r"(b1));
}

// ---------------- per-warp chunk issue ----------------
// chunk c of a tile: 48 warp-rows x 16 cols [c*16, c*16+16).
// c>>2 selects tensor (src|dest|ea|u), (c&3)*16 the col offset within it.
// smem: row stride 64B, quad q stored at q ^ ((row>>1)&3).
DINLINE void issue_chunk(uint32_t slot, long ebase, int E, int c, int lane,
                         const float* __restrict__ s0, const float* __restrict__ s1,
                         const float* __restrict__ s2, const float* __restrict__ u,
                         const void* __restrict__ bat, int is64) {
    const int tensor = c >> 2;
    const int q = lane & 3;
    const int coloff = (c & 3) * 16 + q * 4;
#pragma unroll
    for (int it = 0; it < 6; it++) {
        int row = it * 8 + (lane >> 2);
        long e = ebase + row; if (e >= E) e = E - 1;
        const float* p;
        if (tensor == 0)      p = s0 + e * 64 + coloff;
        else if (tensor == 1) p = s1 + e * 64 + coloff;
        else if (tensor == 2) p = s2 + e * 64 + coloff;
        else {
            long b = is64 ? (long)((const long long*)bat)[e]
                          : (long)((const int*)bat)[e];
            p = u + b * 64 + coloff;
        }
        cp16(slot + (uint32_t)(row * 64) + (uint32_t)((q ^ ((row >> 1) & 3)) << 4), p);
    }
}

// ---------------- kernel ----------------
__global__ void __launch_bounds__(256, 1)
megnet_edge_kernel(const float* __restrict__ src, const float* __restrict__ dst,
                   const float* __restrict__ ea,  const float* __restrict__ u,
                   const int* __restrict__ bat,
                   const float* __restrict__ W1, const float* __restrict__ b1,
                   const float* __restrict__ W2, const float* __restrict__ b2,
                   float* __restrict__ out, int E, int NT) {
    extern __shared__ char smem[];
    const uint32_t sb = s2u(smem);
    const int tid = threadIdx.x;
    const int w = tid >> 5;
    const int lane = tid & 31;

    // ---- one-time: pack W1/W2 into per-lane mma B-fragments (tf32 rna) ----
    // slot s: lane = s&31, nt = (s>>5)&7, kt = s>>8;  b0=W[k][n], b1=W[k+4][n]
    for (int s = tid; s < 8192; s += 256) {
        int l = s & 31, nk = s >> 5, nt = nk & 7, kt = nk >> 3;
        int k = kt * 8 + (l & 3), n = nt * 8 + (l >> 2);
        float2 v = make_float2(tf32r(W1[k * 64 + n]), tf32r(W1[(k + 4) * 64 + n]));
        *(float2*)(smem + OFF_W1F + (size_t)s * 8) = v;
    }
    for (int s = tid; s < 2048; s += 256) {
        int l = s & 31, nk = s >> 5, nt = nk & 7, kt = nk >> 3;
        int k = kt * 8 + (l & 3), n = nt * 8 + (l >> 2);
        float2 v = make_float2(tf32r(W2[k * 64 + n]), tf32r(W2[(k + 4) * 64 + n]));
        *(float2*)(smem + OFF_W2F + (size_t)s * 8) = v;
    }
    if (tid < 64) {
        ((float*)(smem + OFF_B1))[tid] = b1[tid];
        ((float*)(smem + OFF_B2))[tid] = b2[tid];
    }
    if (tid == 0) {
        // batch dtype sniff: int64 payload (values < 2^31) has all-zero odd words
        int is64 = 1;
        for (int i = 1; i < 32; i += 2)
            if (bat[i] != 0) { is64 = 0; break; }
        *(int*)(smem + OFF_FLAG) = is64;
    }
    __syncthreads();
    const int is64 = *(const int*)(smem + OFF_FLAG);
    const float* b1s = (const float*)(smem + OFF_B1);
    const float* b2s = (const float*)(smem + OFF_B2);

    // ---- per-warp constants ----
    const int r0 = lane >> 2;                    // 0..7
    const int l3 = lane & 3;
    const uint32_t ringbase = sb + OFF_CMB + (uint32_t)w * (RING * CHUNK_B);
    const int srcL0 = (lane & 28) | (l3 >> 1);   // shfl owner for cols l3
    const int srcL1 = srcL0 + 2;                 // owner for cols l3+4
    const bool hi = (l3 & 1) != 0;

    const int bid = blockIdx.x, grid = gridDim.x;
    const int numT = (NT - bid + grid - 1) / grid;
    const long total = (long)numT * NCHUNK;

    float C[96];                                 // [m(3)][nt(8)][4]

    // prologue: 4 chunks ahead
#pragma unroll
    for (int pc = 0; pc < 4; pc++) {
        if (pc < total) {
            issue_chunk(ringbase + (uint32_t)(pc % RING) * CHUNK_B,
                        (long)bid * DTILE + w * WROWS, E, pc, lane,
                        src, dst, ea, u, bat, is64);
        }
        cp_commit();   // commit even if empty to keep group count in sync
    }

    for (long n = 0; n < total; n++) {
        const int c = (int)(n & (NCHUNK - 1));
        const long tile = bid + (n >> 4) * grid;

        if (n + 4 < total) {
            long n4 = n + 4;
            issue_chunk(ringbase + (uint32_t)(n4 % RING) * CHUNK_B,
                        (bid + (n4 >> 4) * grid) * DTILE + w * WROWS, E,
                        (int)(n4 & (NCHUNK - 1)), lane,
                        src, dst, ea, u, bat, is64);
            cp_commit();
        }
        cp_wait<4>();          // chunk n landed (4 groups may remain in flight)
        __syncwarp();

        if (c == 0) {
#pragma unroll
            for (int i = 0; i < 96; i++) C[i] = 0.f;
        }

        // ---------- layer-1 partial: 2 k-groups of this chunk ----------
        const char* sbase = smem + OFF_CMB + (size_t)w * (RING * CHUNK_B)
                                 + (size_t)(n % RING) * CHUNK_B;
#pragma unroll
        for (int kg = 0; kg < 2; kg++) {
            const int ktg = c * 2 + kg;
            const uint32_t off0 = (uint32_t)((((2 * kg) ^ (r0 >> 1)) << 4) + l3 * 4);
            uint32_t a[3][4];
#pragma unroll
            for (int m = 0; m < 3; m++) {
                const char* rb = sbase + (m * 16 + r0) * 64;
                a[m][0] = *(const uint32_t*)(rb + off0);
                a[m][1] = *(const uint32_t*)(rb + 512 + off0);
                a[m][2] = *(const uint32_t*)(rb + (off0 ^ 16));
                a[m][3] = *(const uint32_t*)(rb + 512 + (off0 ^ 16));
            }
            const char* wf = smem + OFF_W1F + (size_t)ktg * 2048 + (size_t)lane * 8;
#pragma unroll
            for (int nt = 0; nt < 8; nt++) {
                float2 b = *(const float2*)(wf + nt * 256);
                uint32_t b0 = __float_as_uint(b.x), b1r = __float_as_uint(b.y);
                mma8(C + nt * 4,      a[0][0], a[0][1], a[0][2], a[0][3], b0, b1r);
                mma8(C + 32 + nt * 4, a[1][0], a[1][1], a[1][2], a[1][3], b0, b1r);
                mma8(C + 64 + nt * 4, a[2][0], a[2][1], a[2][2], a[2][3], b0, b1r);
            }
        }

        if (c != NCHUNK - 1) continue;

        // ---------- h = relu(C + b1), tf32 round (in place) ----------
#pragma unroll
        for (int m = 0; m < 3; m++) {
#pragma unroll
            for (int nt = 0; nt < 8; nt++) {
                float2 bb = *(const float2*)(b1s + nt * 8 + 2 * l3);
                float* Cm = C + m * 32 + nt * 4;
                Cm[0] = tf32r(fmaxf(Cm[0] + bb.x, 0.f));
                Cm[1] = tf32r(fmaxf(Cm[1] + bb.y, 0.f));
                Cm[2] = tf32r(fmaxf(Cm[2] + bb.x, 0.f));
                Cm[3] = tf32r(fmaxf(Cm[3] + bb.y, 0.f));
            }
        }

        // ---------- layer 2 per m-sub: A from C via intra-quad shuffles ----------
        const long e0 = tile * DTILE + w * WROWS + r0;
#pragma unroll
        for (int m = 0; m < 3; m++) {
            float C2[32];
#pragma unroll
            for (int i = 0; i < 32; i++) C2[i] = 0.f;
#pragma unroll
            for (int kt = 0; kt < 8; kt++) {
                const float* h = C + m * 32 + kt * 4;
                float v00 = __shfl_sync(0xffffffffu, h[0], srcL0);
                float v01 = __shfl_sync(0xffffffffu, h[1], srcL0);
                float v02 = __shfl_sync(0xffffffffu, h[2], srcL0);
                float v03 = __shfl_sync(0xffffffffu, h[3], srcL0);
                float v10 = __shfl_sync(0xffffffffu, h[0], srcL1);
                float v11 = __shfl_sync(0xffffffffu, h[1], srcL1);
                float v12 = __shfl_sync(0xffffffffu, h[2], srcL1);
                float v13 = __shfl_sync(0xffffffffu, h[3], srcL1);
                uint32_t a0 = __float_as_uint(hi ? v01 : v00);
                uint32_t a1 = __float_as_uint(hi ? v03 : v02);
                uint32_t a2 = __float_as_uint(hi ? v11 : v10);
                uint32_t a3 = __float_as_uint(hi ? v13 : v12);
                const char* wf = smem + OFF_W2F + (size_t)kt * 2048 + (size_t)lane * 8;
#pragma unroll
                for (int nt = 0; nt < 8; nt++) {
                    float2 b = *(const float2*)(wf + nt * 256);
                    mma8(C2 + nt * 4, a0, a1, a2, a3,
                         __float_as_uint(b.x), __float_as_uint(b.y));
                }
            }

            // ---------- out = relu(C2 + b2) -> gmem ----------
            const long e = e0 + m * 16;
#pragma unroll
            for (int nt = 0; nt < 8; nt++) {
                const int col0 = nt * 8 + 2 * l3;
                float2 bb = *(const float2*)(b2s + col0);
                const float* Cm = C2 + nt * 4;
                if (e < E) {
                    float2 v = make_float2(fmaxf(Cm[0] + bb.x, 0.f),
                                           fmaxf(Cm[1] + bb.y, 0.f));
                    *(float2*)(out + e * 64 + col0) = v;
                }
                if (e + 8 < E) {
                    float2 v = make_float2(fmaxf(Cm[2] + bb.x, 0.f),
                                           fmaxf(Cm[3] + bb.y, 0.f));
                    *(float2*)(out + (e + 8) * 64 + col0) = v;
                }
            }
        }
    }
}

// ---------------- launch ----------------
extern "C" void kernel_launch(void* const* d_in, const int* in_sizes, int n_in,
                              void* d_out, int out_size) {
    const float* src = (const float*)d_in[0];
    const float* dst = (const float*)d_in[1];
    const float* ea  = (const float*)d_in[2];
    const float* u   = (const float*)d_in[3];
    const int*   bat = (const int*)d_in[4];   // int32 or int64 payload; sniffed in-kernel
    const float* W1  = (const float*)d_in[5];
    const float* b1  = (const float*)d_in[6];
    const float* W2  = (const float*)d_in[7];
    const float* b2  = (const float*)d_in[8];
    float* out = (float*)d_out;

    int E  = in_sizes[0] / 64;
    int NT = (E + DTILE - 1) / DTILE;

    int dev = 0;
    cudaGetDevice(&dev);
    int nsm = 148;
    cudaDeviceGetAttribute(&nsm, cudaDevAttrMultiProcessorCount, dev);
    int grid = (NT < nsm) ? NT : nsm;

    cudaFuncSetAttribute(megnet_edge_kernel,
                         cudaFuncAttributeMaxDynamicSharedMemorySize, SMEM_TOTAL);
    megnet_edge_kernel<<<grid, 256, SMEM_TOTAL>>>(src, dst, ea, u, bat,
                                                  W1, b1, W2, b2, out, E, NT);
    (void)n_in; (void)out_size;
}